// round 15
// baseline (speedup 1.0000x reference)
#include <cuda_runtime.h>
#include <cuda_fp16.h>

#define BATCH   128
#define NUM_IN  4096
#define NLEV    8
#define H       32768
#define KFAN    32
#define NOUT    256
#define KOUT    64
#define SCALE   4.9f

#define NODES   (NUM_IN + NLEV * H)   // 266240 nodes, node-major

// Node-major activation buffer in fp16: buf[node * BATCH + b].  ~65 MB scratch.
__device__ __align__(256) __half g_buf[(size_t)NODES * BATCH];

__device__ __forceinline__ float fast_sigmoid(float x) {
    return 1.0f / (1.0f + __expf(-x));
}

// --- PDL primitives (sm_90+) ---
__device__ __forceinline__ void pdl_trigger() {
    asm volatile("griddepcontrol.launch_dependents;");
}
__device__ __forceinline__ void pdl_wait() {
    asm volatile("griddepcontrol.wait;" ::: "memory");
}

// Gather 4 consecutive batch halves (8B) for node n at batch-quad `lane`.
__device__ __forceinline__ float4 gather4(const __half* __restrict__ buf, int n, int lane) {
    const uint2 raw = __ldg((const uint2*)(buf + (size_t)n * BATCH + lane * 4));
    const __half2 h01 = *(const __half2*)&raw.x;
    const __half2 h23 = *(const __half2*)&raw.y;
    const float2 f01 = __half22float2(h01);
    const float2 f23 = __half22float2(h23);
    return make_float4(f01.x, f01.y, f23.x, f23.y);
}

// ---------------------------------------------------------------------------
// Kernel 1: coalesced transpose+quantize x [B, NUM_IN] -> g_buf (node-major).
// ---------------------------------------------------------------------------
__global__ void __launch_bounds__(128) init_buf_kernel(const float* __restrict__ x) {
    pdl_trigger();                    // let level 0 start launching early
    __shared__ float tile[32][133];
    const int t  = threadIdx.x;
    const int n0 = blockIdx.x * 32;

    const int ni = t & 31;
    const int b4 = t >> 5;
#pragma unroll
    for (int c = 0; c < 32; ++c) {
        const int b = c * 4 + b4;
        tile[ni][b] = __ldg(&x[(size_t)b * NUM_IN + n0 + ni]);
    }
    __syncthreads();

    const int nn = t >> 2;
    const int q  = t & 3;
#pragma unroll
    for (int j = 0; j < 8; ++j) {
        const int b = q * 32 + j * 4;
        const __half2 h01 = __floats2half2_rn(tile[nn][b + 0], tile[nn][b + 1]);
        const __half2 h23 = __floats2half2_rn(tile[nn][b + 2], tile[nn][b + 3]);
        uint2 p;
        p.x = *(const unsigned int*)&h01;
        p.y = *(const unsigned int*)&h23;
        *(uint2*)(g_buf + (size_t)(n0 + nn) * BATCH + b) = p;
    }
}

// ---------------------------------------------------------------------------
// Kernel 2: one topological level.  EXACT R3/R14 champion body (runs at the
// LTS byte cap). PDL added: trigger at entry so the next level launches and
// stages onto freed SMs during this grid's tail; wait (full completion +
// memory visibility of the previous level) guards the first gather.
// ---------------------------------------------------------------------------
__global__ void __launch_bounds__(BATCH, 8) level_kernel(
    const float* __restrict__ w,    // [H, K] for this level
    const int*   __restrict__ idx,  // [H, K] for this level
    int base)                       // first output node id of this level
{
    pdl_trigger();

    const int lane = threadIdx.x & 31;   // batch quad: 4*lane .. 4*lane+3
    const int wid  = threadIdx.x >> 5;
    const int h    = blockIdx.x * 4 + wid;

    const int4*   ip4 = (const int4*)  (idx + (size_t)h * KFAN);
    const float4* wp4 = (const float4*)(w   + (size_t)h * KFAN);

    // Prologue (independent of g_buf): first index/weight pair can load
    // while the previous level is still draining.
    const int4   i4_0 = __ldg(ip4 + 0);
    const float4 w4_0 = __ldg(wp4 + 0);

    pdl_wait();   // previous level fully complete + visible

    float ax = 0.f, ay = 0.f, az = 0.f, aw = 0.f;

#pragma unroll
    for (int kk = 0; kk < KFAN / 4; ++kk) {
        const int4   i4 = (kk == 0) ? i4_0 : __ldg(ip4 + kk);
        const float4 w4 = (kk == 0) ? w4_0 : __ldg(wp4 + kk);

        const float4 v0 = gather4(g_buf, i4.x, lane);
        const float4 v1 = gather4(g_buf, i4.y, lane);
        const float4 v2 = gather4(g_buf, i4.z, lane);
        const float4 v3 = gather4(g_buf, i4.w, lane);

        ax = fmaf(w4.x, v0.x, ax); ay = fmaf(w4.x, v0.y, ay);
        az = fmaf(w4.x, v0.z, az); aw = fmaf(w4.x, v0.w, aw);

        ax = fmaf(w4.y, v1.x, ax); ay = fmaf(w4.y, v1.y, ay);
        az = fmaf(w4.y, v1.z, az); aw = fmaf(w4.y, v1.w, aw);

        ax = fmaf(w4.z, v2.x, ax); ay = fmaf(w4.z, v2.y, ay);
        az = fmaf(w4.z, v2.z, az); aw = fmaf(w4.z, v2.w, aw);

        ax = fmaf(w4.w, v3.x, ax); ay = fmaf(w4.w, v3.y, ay);
        az = fmaf(w4.w, v3.z, az); aw = fmaf(w4.w, v3.w, aw);
    }

    const __half2 r01 = __floats2half2_rn(fast_sigmoid(SCALE * ax),
                                          fast_sigmoid(SCALE * ay));
    const __half2 r23 = __floats2half2_rn(fast_sigmoid(SCALE * az),
                                          fast_sigmoid(SCALE * aw));
    uint2 packed;
    packed.x = *(const unsigned int*)&r01;
    packed.y = *(const unsigned int*)&r23;
    *(uint2*)(g_buf + (size_t)(base + h) * BATCH + lane * 4) = packed;
}

// ---------------------------------------------------------------------------
// Kernel 3: output layer (tiny). One warp per output unit, fp32 accumulation.
// ---------------------------------------------------------------------------
__global__ void __launch_bounds__(BATCH) output_kernel(
    const float* __restrict__ w_out,   // [O, KO]
    const int*   __restrict__ idx_out, // [O, KO]
    float*       __restrict__ out)     // [B, O]
{
    pdl_trigger();

    const int lane = threadIdx.x & 31;
    const int wid  = threadIdx.x >> 5;
    const int o    = blockIdx.x * 4 + wid;

    const int4*   ip4 = (const int4*)  (idx_out + (size_t)o * KOUT);
    const float4* wp4 = (const float4*)(w_out   + (size_t)o * KOUT);

    pdl_wait();   // level 7 fully complete + visible

    float ax = 0.f, ay = 0.f, az = 0.f, aw = 0.f;

#pragma unroll
    for (int kk = 0; kk < KOUT / 4; ++kk) {
        const int4   i4 = __ldg(ip4 + kk);
        const float4 w4 = __ldg(wp4 + kk);

        const float4 v0 = gather4(g_buf, i4.x, lane);
        const float4 v1 = gather4(g_buf, i4.y, lane);
        const float4 v2 = gather4(g_buf, i4.z, lane);
        const float4 v3 = gather4(g_buf, i4.w, lane);

        ax = fmaf(w4.x, v0.x, ax); ay = fmaf(w4.x, v0.y, ay);
        az = fmaf(w4.x, v0.z, az); aw = fmaf(w4.x, v0.w, aw);
        ax = fmaf(w4.y, v1.x, ax); ay = fmaf(w4.y, v1.y, ay);
        az = fmaf(w4.y, v1.z, az); aw = fmaf(w4.y, v1.w, aw);
        ax = fmaf(w4.z, v2.x, ax); ay = fmaf(w4.z, v2.y, ay);
        az = fmaf(w4.z, v2.z, az); aw = fmaf(w4.z, v2.w, aw);
        ax = fmaf(w4.w, v3.x, ax); ay = fmaf(w4.w, v3.y, ay);
        az = fmaf(w4.w, v3.z, az); aw = fmaf(w4.w, v3.w, aw);
    }

    const int b0 = lane * 4;
    out[(size_t)(b0 + 0) * NOUT + o] = fast_sigmoid(SCALE * ax);
    out[(size_t)(b0 + 1) * NOUT + o] = fast_sigmoid(SCALE * ay);
    out[(size_t)(b0 + 2) * NOUT + o] = fast_sigmoid(SCALE * az);
    out[(size_t)(b0 + 3) * NOUT + o] = fast_sigmoid(SCALE * aw);
}

// ---------------------------------------------------------------------------
// Launch: 1 init + 8 level + 1 output kernels chained with PDL
// (programmatic stream serialization). All graph-capturable.
// Input order (metadata): x, w_hidden, w_out, idx_hidden, idx_out.
// ---------------------------------------------------------------------------
extern "C" void kernel_launch(void* const* d_in, const int* in_sizes, int n_in,
                              void* d_out, int out_size) {
    const float* x        = (const float*)d_in[0];
    const float* w_hidden = (const float*)d_in[1];  // [L, H, K]
    const float* w_out    = (const float*)d_in[2];  // [O, KO]
    const int*   idx_hid  = (const int*)  d_in[3];  // [L, H, K]
    const int*   idx_out  = (const int*)  d_in[4];  // [O, KO]
    float*       out      = (float*)d_out;          // [B, O]

    cudaLaunchAttribute pdl_attr[1];
    pdl_attr[0].id = cudaLaunchAttributeProgrammaticStreamSerialization;
    pdl_attr[0].val.programmaticStreamSerializationAllowed = 1;

    // init (ordinary launch; calls trigger so level 0 can overlap its tail)
    init_buf_kernel<<<NUM_IN / 32, 128>>>(x);

    // 8 levels, each PDL-dependent on its predecessor
    for (int l = 0; l < NLEV; ++l) {
        const float* wl = w_hidden + (size_t)l * H * KFAN;
        const int*   il = idx_hid  + (size_t)l * H * KFAN;

        cudaLaunchConfig_t cfg = {};
        cfg.gridDim  = dim3(H / 4);
        cfg.blockDim = dim3(BATCH);
        cfg.attrs    = pdl_attr;
        cfg.numAttrs = 1;
        cudaLaunchKernelEx(&cfg, level_kernel, wl, il, NUM_IN + l * H);
    }

    // output, PDL-dependent on level 7
    {
        cudaLaunchConfig_t cfg = {};
        cfg.gridDim  = dim3(NOUT / 4);
        cfg.blockDim = dim3(BATCH);
        cfg.attrs    = pdl_attr;
        cfg.numAttrs = 1;
        cudaLaunchKernelEx(&cfg, output_kernel, w_out, idx_out, out);
    }
}

// round 16
// speedup vs baseline: 1.0125x; 1.0125x over previous
#include <cuda_runtime.h>
#include <cuda_fp16.h>

#define BATCH   128
#define NUM_IN  4096
#define NLEV    8
#define H       32768
#define KFAN    32
#define NOUT    256
#define KOUT    64
#define SCALE   4.9f

#define NODES   (NUM_IN + NLEV * H)   // 266240 nodes, node-major

// Node-major activation buffer in fp16: buf[node * BATCH + b].  ~65 MB scratch.
// fp16 is the minimum precision meeting rel_err < 1e-3 (measured 1.43e-4;
// u8 predicts ~5e-3, rejected). At fp16, the 8 level kernels run at the
// HW-measured full-chip LTS byte cap (~6.2 KB/cyc) -- the workload floor.
__device__ __align__(256) __half g_buf[(size_t)NODES * BATCH];

__device__ __forceinline__ float fast_sigmoid(float x) {
    return 1.0f / (1.0f + __expf(-x));
}

// Gather 4 consecutive batch halves (8B) for node n at batch-quad `lane`.
__device__ __forceinline__ float4 gather4(const __half* __restrict__ buf, int n, int lane) {
    const uint2 raw = __ldg((const uint2*)(buf + (size_t)n * BATCH + lane * 4));
    const __half2 h01 = *(const __half2*)&raw.x;
    const __half2 h23 = *(const __half2*)&raw.y;
    const float2 f01 = __half22float2(h01);
    const float2 f23 = __half22float2(h23);
    return make_float4(f01.x, f01.y, f23.x, f23.y);
}

// ---------------------------------------------------------------------------
// Kernel 1: coalesced transpose+quantize x [B, NUM_IN] -> g_buf (node-major).
// Block covers a 32-node x 128-batch tile via smem; both sides coalesced.
// ---------------------------------------------------------------------------
__global__ void __launch_bounds__(128) init_buf_kernel(const float* __restrict__ x) {
    __shared__ float tile[32][133];   // stride 133: conflict-free
    const int t  = threadIdx.x;
    const int n0 = blockIdx.x * 32;

    const int ni = t & 31;
    const int b4 = t >> 5;
#pragma unroll
    for (int c = 0; c < 32; ++c) {
        const int b = c * 4 + b4;
        tile[ni][b] = __ldg(&x[(size_t)b * NUM_IN + n0 + ni]);
    }
    __syncthreads();

    const int nn = t >> 2;
    const int q  = t & 3;
#pragma unroll
    for (int j = 0; j < 8; ++j) {
        const int b = q * 32 + j * 4;
        const __half2 h01 = __floats2half2_rn(tile[nn][b + 0], tile[nn][b + 1]);
        const __half2 h23 = __floats2half2_rn(tile[nn][b + 2], tile[nn][b + 3]);
        uint2 p;
        p.x = *(const unsigned int*)&h01;
        p.y = *(const unsigned int*)&h23;
        *(uint2*)(g_buf + (size_t)(n0 + nn) * BATCH + b) = p;
    }
}

// ---------------------------------------------------------------------------
// Kernel 2: one topological level.  Converged champion body: one warp per
// hidden unit; each lane owns a batch quad (uint2 = 4 halves, 256B coalesced
// per warp-gather); fp32 convert + FMA accumulation. Runs at the LTS byte
// cap; every structural variant tried across 13 rounds (MLP widening, HFMA2,
// SMEM staging, cp.async, fusion, PDL, occupancy trades) measured >= this.
// ---------------------------------------------------------------------------
__global__ void __launch_bounds__(BATCH, 8) level_kernel(
    const float* __restrict__ w,    // [H, K] for this level
    const int*   __restrict__ idx,  // [H, K] for this level
    int base)                       // first output node id of this level
{
    const int lane = threadIdx.x & 31;   // batch quad: 4*lane .. 4*lane+3
    const int wid  = threadIdx.x >> 5;
    const int h    = blockIdx.x * 4 + wid;

    const int4*   ip4 = (const int4*)  (idx + (size_t)h * KFAN);
    const float4* wp4 = (const float4*)(w   + (size_t)h * KFAN);

    float ax = 0.f, ay = 0.f, az = 0.f, aw = 0.f;

#pragma unroll
    for (int kk = 0; kk < KFAN / 4; ++kk) {
        const int4   i4 = __ldg(ip4 + kk);   // warp-uniform broadcast
        const float4 w4 = __ldg(wp4 + kk);

        const float4 v0 = gather4(g_buf, i4.x, lane);
        const float4 v1 = gather4(g_buf, i4.y, lane);
        const float4 v2 = gather4(g_buf, i4.z, lane);
        const float4 v3 = gather4(g_buf, i4.w, lane);

        ax = fmaf(w4.x, v0.x, ax); ay = fmaf(w4.x, v0.y, ay);
        az = fmaf(w4.x, v0.z, az); aw = fmaf(w4.x, v0.w, aw);

        ax = fmaf(w4.y, v1.x, ax); ay = fmaf(w4.y, v1.y, ay);
        az = fmaf(w4.y, v1.z, az); aw = fmaf(w4.y, v1.w, aw);

        ax = fmaf(w4.z, v2.x, ax); ay = fmaf(w4.z, v2.y, ay);
        az = fmaf(w4.z, v2.z, az); aw = fmaf(w4.z, v2.w, aw);

        ax = fmaf(w4.w, v3.x, ax); ay = fmaf(w4.w, v3.y, ay);
        az = fmaf(w4.w, v3.z, az); aw = fmaf(w4.w, v3.w, aw);
    }

    const __half2 r01 = __floats2half2_rn(fast_sigmoid(SCALE * ax),
                                          fast_sigmoid(SCALE * ay));
    const __half2 r23 = __floats2half2_rn(fast_sigmoid(SCALE * az),
                                          fast_sigmoid(SCALE * aw));
    uint2 packed;
    packed.x = *(const unsigned int*)&r01;
    packed.y = *(const unsigned int*)&r23;
    *(uint2*)(g_buf + (size_t)(base + h) * BATCH + lane * 4) = packed;
}

// ---------------------------------------------------------------------------
// Kernel 3: output layer (tiny). One warp per output unit, fp32 accumulation.
// ---------------------------------------------------------------------------
__global__ void __launch_bounds__(BATCH) output_kernel(
    const float* __restrict__ w_out,   // [O, KO]
    const int*   __restrict__ idx_out, // [O, KO]
    float*       __restrict__ out)     // [B, O]
{
    const int lane = threadIdx.x & 31;
    const int wid  = threadIdx.x >> 5;
    const int o    = blockIdx.x * 4 + wid;

    const int4*   ip4 = (const int4*)  (idx_out + (size_t)o * KOUT);
    const float4* wp4 = (const float4*)(w_out   + (size_t)o * KOUT);

    float ax = 0.f, ay = 0.f, az = 0.f, aw = 0.f;

#pragma unroll
    for (int kk = 0; kk < KOUT / 4; ++kk) {
        const int4   i4 = __ldg(ip4 + kk);
        const float4 w4 = __ldg(wp4 + kk);

        const float4 v0 = gather4(g_buf, i4.x, lane);
        const float4 v1 = gather4(g_buf, i4.y, lane);
        const float4 v2 = gather4(g_buf, i4.z, lane);
        const float4 v3 = gather4(g_buf, i4.w, lane);

        ax = fmaf(w4.x, v0.x, ax); ay = fmaf(w4.x, v0.y, ay);
        az = fmaf(w4.x, v0.z, az); aw = fmaf(w4.x, v0.w, aw);
        ax = fmaf(w4.y, v1.x, ax); ay = fmaf(w4.y, v1.y, ay);
        az = fmaf(w4.y, v1.z, az); aw = fmaf(w4.y, v1.w, aw);
        ax = fmaf(w4.z, v2.x, ax); ay = fmaf(w4.z, v2.y, ay);
        az = fmaf(w4.z, v2.z, az); aw = fmaf(w4.z, v2.w, aw);
        ax = fmaf(w4.w, v3.x, ax); ay = fmaf(w4.w, v3.y, ay);
        az = fmaf(w4.w, v3.z, az); aw = fmaf(w4.w, v3.w, aw);
    }

    const int b0 = lane * 4;
    out[(size_t)(b0 + 0) * NOUT + o] = fast_sigmoid(SCALE * ax);
    out[(size_t)(b0 + 1) * NOUT + o] = fast_sigmoid(SCALE * ay);
    out[(size_t)(b0 + 2) * NOUT + o] = fast_sigmoid(SCALE * az);
    out[(size_t)(b0 + 3) * NOUT + o] = fast_sigmoid(SCALE * aw);
}

// ---------------------------------------------------------------------------
// Launch: 1 init + 8 level + 1 output kernels, all graph-capturable.
// Input order (metadata): x, w_hidden, w_out, idx_hidden, idx_out.
// ---------------------------------------------------------------------------
extern "C" void kernel_launch(void* const* d_in, const int* in_sizes, int n_in,
                              void* d_out, int out_size) {
    const float* x        = (const float*)d_in[0];
    const float* w_hidden = (const float*)d_in[1];  // [L, H, K]
    const float* w_out    = (const float*)d_in[2];  // [O, KO]
    const int*   idx_hid  = (const int*)  d_in[3];  // [L, H, K]
    const int*   idx_out  = (const int*)  d_in[4];  // [O, KO]
    float*       out      = (float*)d_out;          // [B, O]

    init_buf_kernel<<<NUM_IN / 32, 128>>>(x);

    for (int l = 0; l < NLEV; ++l) {
        const float* wl = w_hidden + (size_t)l * H * KFAN;
        const int*   il = idx_hid  + (size_t)l * H * KFAN;
        level_kernel<<<H / 4, BATCH>>>(wl, il, NUM_IN + l * H);
    }

    output_kernel<<<NOUT / 4, BATCH>>>(w_out, idx_out, out);
}

// round 17
// speedup vs baseline: 1.0366x; 1.0238x over previous
#include <cuda_runtime.h>
#include <cuda_fp16.h>

#define BATCH   128
#define NUM_IN  4096
#define NLEV    8
#define H       32768
#define KFAN    32
#define NOUT    256
#define KOUT    64
#define SCALE   4.9f

#define NODES   (NUM_IN + NLEV * H)   // 266240 nodes, node-major
#define L5BASE  (NUM_IN + 5 * H)      // first node id of level 5

// Node-major activation buffer in fp16: buf[node * BATCH + b].  ~65 MB scratch.
__device__ __align__(256) __half g_buf[(size_t)NODES * BATCH];

// Liveness scratch for levels 5..7 (slot 0=L5, 1=L6, 2=L7).
__device__ unsigned char g_flag[3 * H];
__device__ int           g_list[3][H];
__device__ int           g_count[3];

__device__ __forceinline__ float fast_sigmoid(float x) {
    return 1.0f / (1.0f + __expf(-x));
}

// Gather 4 consecutive batch halves (8B) for node n at batch-quad `lane`.
__device__ __forceinline__ float4 gather4(const __half* __restrict__ buf, int n, int lane) {
    const uint2 raw = __ldg((const uint2*)(buf + (size_t)n * BATCH + lane * 4));
    const float2 f01 = __half22float2(*(const __half2*)&raw.x);
    const float2 f23 = __half22float2(*(const __half2*)&raw.y);
    return make_float4(f01.x, f01.y, f23.x, f23.y);
}

// ---------------------------------------------------------------------------
// Liveness kernels (pure function of idx arrays -> deterministic per launch).
// ---------------------------------------------------------------------------
__global__ void liveness_clear_kernel() {
    const int t = blockIdx.x * blockDim.x + threadIdx.x;
    if (t < 3 * H) g_flag[t] = 0;
    if (t < 3)     g_count[t] = 0;
}

__global__ void mark_out_kernel(const int* __restrict__ idx_out) {
    const int t = blockIdx.x * blockDim.x + threadIdx.x;   // < NOUT*KOUT
    const int v = __ldg(idx_out + t);
    if (v >= L5BASE) g_flag[v - L5BASE] = 1;
}

// Compact flagged units of one level into g_list[slot] (warp-aggregated).
__global__ void compact_kernel(int slot) {
    const int u    = blockIdx.x * blockDim.x + threadIdx.x;   // < H
    const int lane = threadIdx.x & 31;
    const int flagged = g_flag[slot * H + u];
    const unsigned m  = __ballot_sync(0xffffffffu, flagged);
    int base = 0;
    if (lane == 0) {
        const int n = __popc(m);
        if (n) base = atomicAdd(&g_count[slot], n);
    }
    base = __shfl_sync(0xffffffffu, base, 0);
    if (flagged)
        g_list[slot][base + __popc(m & ((1u << lane) - 1u))] = u;
}

// Mark the fan-in (levels >= 5 only) of every live unit in g_list[slot].
__global__ void mark_list_kernel(const int* __restrict__ idx, int slot) {
    const int t   = blockIdx.x * blockDim.x + threadIdx.x;   // < H*32
    const int pos = t >> 5;
    if (pos >= g_count[slot]) return;
    const int u = g_list[slot][pos];
    const int v = __ldg(idx + u * KFAN + (t & 31));
    if (v >= L5BASE) g_flag[v - L5BASE] = 1;
}

// ---------------------------------------------------------------------------
// Kernel 1: coalesced transpose+quantize x [B, NUM_IN] -> g_buf (node-major).
// ---------------------------------------------------------------------------
__global__ void __launch_bounds__(128) init_buf_kernel(const float* __restrict__ x) {
    __shared__ float tile[32][133];
    const int t  = threadIdx.x;
    const int n0 = blockIdx.x * 32;

    const int ni = t & 31;
    const int b4 = t >> 5;
#pragma unroll
    for (int c = 0; c < 32; ++c) {
        const int b = c * 4 + b4;
        tile[ni][b] = __ldg(&x[(size_t)b * NUM_IN + n0 + ni]);
    }
    __syncthreads();

    const int nn = t >> 2;
    const int q  = t & 3;
#pragma unroll
    for (int j = 0; j < 8; ++j) {
        const int b = q * 32 + j * 4;
        const __half2 h01 = __floats2half2_rn(tile[nn][b + 0], tile[nn][b + 1]);
        const __half2 h23 = __floats2half2_rn(tile[nn][b + 2], tile[nn][b + 3]);
        uint2 p;
        p.x = *(const unsigned int*)&h01;
        p.y = *(const unsigned int*)&h23;
        *(uint2*)(g_buf + (size_t)(n0 + nn) * BATCH + b) = p;
    }
}

// Champion per-unit body, shared by dense and sparse level kernels.
__device__ __forceinline__ void compute_unit(
    const float* __restrict__ w, const int* __restrict__ idx,
    int base, int h, int lane)
{
    const int4*   ip4 = (const int4*)  (idx + (size_t)h * KFAN);
    const float4* wp4 = (const float4*)(w   + (size_t)h * KFAN);

    float ax = 0.f, ay = 0.f, az = 0.f, aw = 0.f;

#pragma unroll
    for (int kk = 0; kk < KFAN / 4; ++kk) {
        const int4   i4 = __ldg(ip4 + kk);   // warp-uniform broadcast
        const float4 w4 = __ldg(wp4 + kk);

        const float4 v0 = gather4(g_buf, i4.x, lane);
        const float4 v1 = gather4(g_buf, i4.y, lane);
        const float4 v2 = gather4(g_buf, i4.z, lane);
        const float4 v3 = gather4(g_buf, i4.w, lane);

        ax = fmaf(w4.x, v0.x, ax); ay = fmaf(w4.x, v0.y, ay);
        az = fmaf(w4.x, v0.z, az); aw = fmaf(w4.x, v0.w, aw);
        ax = fmaf(w4.y, v1.x, ax); ay = fmaf(w4.y, v1.y, ay);
        az = fmaf(w4.y, v1.z, az); aw = fmaf(w4.y, v1.w, aw);
        ax = fmaf(w4.z, v2.x, ax); ay = fmaf(w4.z, v2.y, ay);
        az = fmaf(w4.z, v2.z, az); aw = fmaf(w4.z, v2.w, aw);
        ax = fmaf(w4.w, v3.x, ax); ay = fmaf(w4.w, v3.y, ay);
        az = fmaf(w4.w, v3.z, az); aw = fmaf(w4.w, v3.w, aw);
    }

    const __half2 r01 = __floats2half2_rn(fast_sigmoid(SCALE * ax),
                                          fast_sigmoid(SCALE * ay));
    const __half2 r23 = __floats2half2_rn(fast_sigmoid(SCALE * az),
                                          fast_sigmoid(SCALE * aw));
    uint2 packed;
    packed.x = *(const unsigned int*)&r01;
    packed.y = *(const unsigned int*)&r23;
    *(uint2*)(g_buf + (size_t)(base + h) * BATCH + lane * 4) = packed;
}

// ---------------------------------------------------------------------------
// Kernel 2a: dense level (levels 0..4). Exact champion configuration.
// ---------------------------------------------------------------------------
__global__ void __launch_bounds__(BATCH, 8) level_kernel(
    const float* __restrict__ w, const int* __restrict__ idx, int base)
{
    const int lane = threadIdx.x & 31;
    const int h    = blockIdx.x * 4 + (threadIdx.x >> 5);
    compute_unit(w, idx, base, h, lane);
}

// ---------------------------------------------------------------------------
// Kernel 2b: sparse level (levels 5..7): only live units (g_list[slot]).
// Static full grid (graph-safe); warps past count exit immediately.
// ---------------------------------------------------------------------------
__global__ void __launch_bounds__(BATCH, 8) sparse_level_kernel(
    const float* __restrict__ w, const int* __restrict__ idx, int base, int slot)
{
    const int lane = threadIdx.x & 31;
    const int pos  = blockIdx.x * 4 + (threadIdx.x >> 5);
    if (pos >= g_count[slot]) return;
    const int h = g_list[slot][pos];
    compute_unit(w, idx, base, h, lane);
}

// ---------------------------------------------------------------------------
// Kernel 3: output layer. One warp per output unit, fp32 accumulation.
// ---------------------------------------------------------------------------
__global__ void __launch_bounds__(BATCH) output_kernel(
    const float* __restrict__ w_out,
    const int*   __restrict__ idx_out,
    float*       __restrict__ out)
{
    const int lane = threadIdx.x & 31;
    const int o    = blockIdx.x * 4 + (threadIdx.x >> 5);

    const int4*   ip4 = (const int4*)  (idx_out + (size_t)o * KOUT);
    const float4* wp4 = (const float4*)(w_out   + (size_t)o * KOUT);

    float ax = 0.f, ay = 0.f, az = 0.f, aw = 0.f;

#pragma unroll
    for (int kk = 0; kk < KOUT / 4; ++kk) {
        const int4   i4 = __ldg(ip4 + kk);
        const float4 w4 = __ldg(wp4 + kk);

        const float4 v0 = gather4(g_buf, i4.x, lane);
        const float4 v1 = gather4(g_buf, i4.y, lane);
        const float4 v2 = gather4(g_buf, i4.z, lane);
        const float4 v3 = gather4(g_buf, i4.w, lane);

        ax = fmaf(w4.x, v0.x, ax); ay = fmaf(w4.x, v0.y, ay);
        az = fmaf(w4.x, v0.z, az); aw = fmaf(w4.x, v0.w, aw);
        ax = fmaf(w4.y, v1.x, ax); ay = fmaf(w4.y, v1.y, ay);
        az = fmaf(w4.y, v1.z, az); aw = fmaf(w4.y, v1.w, aw);
        ax = fmaf(w4.z, v2.x, ax); ay = fmaf(w4.z, v2.y, ay);
        az = fmaf(w4.z, v2.z, az); aw = fmaf(w4.z, v2.w, aw);
        ax = fmaf(w4.w, v3.x, ax); ay = fmaf(w4.w, v3.y, ay);
        az = fmaf(w4.w, v3.z, az); aw = fmaf(w4.w, v3.w, aw);
    }

    const int b0 = lane * 4;
    out[(size_t)(b0 + 0) * NOUT + o] = fast_sigmoid(SCALE * ax);
    out[(size_t)(b0 + 1) * NOUT + o] = fast_sigmoid(SCALE * ay);
    out[(size_t)(b0 + 2) * NOUT + o] = fast_sigmoid(SCALE * az);
    out[(size_t)(b0 + 3) * NOUT + o] = fast_sigmoid(SCALE * aw);
}

// ---------------------------------------------------------------------------
// Launch. Liveness pass (pure function of idx arrays) prunes dead units in
// levels 5..7 (expected live: ~83% / ~28% / ~6%). All graph-capturable.
// Input order (metadata): x, w_hidden, w_out, idx_hidden, idx_out.
// ---------------------------------------------------------------------------
extern "C" void kernel_launch(void* const* d_in, const int* in_sizes, int n_in,
                              void* d_out, int out_size) {
    const float* x        = (const float*)d_in[0];
    const float* w_hidden = (const float*)d_in[1];  // [L, H, K]
    const float* w_out    = (const float*)d_in[2];  // [O, KO]
    const int*   idx_hid  = (const int*)  d_in[3];  // [L, H, K]
    const int*   idx_out  = (const int*)  d_in[4];  // [O, KO]
    float*       out      = (float*)d_out;          // [B, O]

    const int* idx5 = idx_hid + (size_t)5 * H * KFAN;
    const int* idx6 = idx_hid + (size_t)6 * H * KFAN;
    const int* idx7 = idx_hid + (size_t)7 * H * KFAN;

    init_buf_kernel<<<NUM_IN / 32, 128>>>(x);

    // Backward liveness: out -> L7 -> L6 -> L5.
    liveness_clear_kernel<<<(3 * H + 255) / 256, 256>>>();
    mark_out_kernel<<<(NOUT * KOUT) / 256, 256>>>(idx_out);
    compact_kernel<<<H / 256, 256>>>(2);                 // live L7
    mark_list_kernel<<<(H * 32) / 256, 256>>>(idx7, 2);  // fan-in of live L7
    compact_kernel<<<H / 256, 256>>>(1);                 // live L6
    mark_list_kernel<<<(H * 32) / 256, 256>>>(idx6, 1);  // fan-in of live L6
    compact_kernel<<<H / 256, 256>>>(0);                 // live L5

    // Levels 0..4 dense (≈100% live).
    for (int l = 0; l < 5; ++l) {
        const float* wl = w_hidden + (size_t)l * H * KFAN;
        const int*   il = idx_hid  + (size_t)l * H * KFAN;
        level_kernel<<<H / 4, BATCH>>>(wl, il, NUM_IN + l * H);
    }

    // Levels 5..7 sparse (live units only).
    sparse_level_kernel<<<H / 4, BATCH>>>(w_hidden + (size_t)5 * H * KFAN, idx5,
                                          NUM_IN + 5 * H, 0);
    sparse_level_kernel<<<H / 4, BATCH>>>(w_hidden + (size_t)6 * H * KFAN, idx6,
                                          NUM_IN + 6 * H, 1);
    sparse_level_kernel<<<H / 4, BATCH>>>(w_hidden + (size_t)7 * H * KFAN, idx7,
                                          NUM_IN + 7 * H, 2);

    output_kernel<<<NOUT / 4, BATCH>>>(w_out, idx_out, out);
}